// round 4
// baseline (speedup 1.0000x reference)
#include <cuda_runtime.h>
#include <math.h>

#define B 512
#define NN 24
#define T 25
#define OUTF 128
#define G4 512
#define K0 72

__device__ float g_xi[NN*B*K0];
__device__ float g_h1[NN*B*OUTF];
__device__ float g_c1[NN*B*OUTF];
__device__ float g_h2[NN*B*OUTF];
__device__ float g_c2[NN*B*OUTF];
__device__ float g_yi[NN*B*OUTF];
__device__ float g_gates[NN*B*G4];
__device__ float g_t1[NN*B*OUTF];
__device__ float g_t2[NN*B*OUTF];
__device__ float g_ls[NN*B*4];

typedef unsigned long long u64;
__device__ __forceinline__ u64 ffma2(u64 a,u64 b,u64 c){u64 d;asm("fma.rn.f32x2 %0,%1,%2,%3;":"=l"(d):"l"(a),"l"(b),"l"(c));return d;}
__device__ __forceinline__ u64 pk2(float x,float y){u64 r;asm("mov.b64 %0,{%1,%2};":"=l"(r):"f"(x),"f"(y));return r;}
__device__ __forceinline__ float2 upk2(u64 v){float2 r;asm("mov.b64 {%0,%1},%2;":"=f"(r.x),"=f"(r.y):"l"(v));return r;}
__device__ __forceinline__ float sigf(float x){return 1.f/(1.f+expf(-x));}

// C[n][row][0..NO) = bias[n] + A1[n,row,:K1]@W1[n] + A2[n,row,:K2]@W2[n]
__global__ __launch_bounds__(256) void gemm_dual(
  const float* __restrict__ A1, long long sA1n, int sA1r, int K1,
  const float* __restrict__ W1, long long sW1n,
  const float* __restrict__ A2, long long sA2n, int sA2r, int K2,
  const float* __restrict__ W2, long long sW2n,
  const float* __restrict__ bias, int sbn,
  float* __restrict__ C, int NO)
{
  const int n = blockIdx.z, row0 = blockIdx.y*64, col0 = blockIdx.x*128;
  const int tid = threadIdx.x;
  __shared__ u64 As2[8][64];
  __shared__ float Ws[8][128];
  u64 acc[4][4];
  #pragma unroll
  for(int i=0;i<4;i++){
    #pragma unroll
    for(int j=0;j<4;j++) acc[i][j]=0ull;
  }
  const int trow=(tid>>4)*4, tcol=(tid&15)*8;
  const int la_r=tid>>2, la_k=(tid&3)*2;
  const int lw_k=tid>>5, lw_c=(tid&31)*4;
  #pragma unroll 1
  for(int seg=0;seg<2;seg++){
    const float* A; int sAr; const float* W; int K;
    if(seg==0){K=K1;if(K<=0)continue;A=A1+(long long)n*sA1n;sAr=sA1r;W=W1+(long long)n*sW1n;}
    else      {K=K2;if(K<=0)continue;A=A2+(long long)n*sA2n;sAr=sA2r;W=W2+(long long)n*sW2n;}
    const float* aP=A+(long long)(row0+la_r)*sAr+la_k;
    const float* wP=W+(long long)lw_k*NO+col0+lw_c;
    float2 aR=*(const float2*)aP;
    float4 wR=*(const float4*)wP;
    #pragma unroll 1
    for(int k0=0;k0<K;k0+=8){
      __syncthreads();
      As2[la_k  ][la_r]=pk2(aR.x,aR.x);
      As2[la_k+1][la_r]=pk2(aR.y,aR.y);
      *(float4*)&Ws[lw_k][lw_c]=wR;
      __syncthreads();
      if(k0+8<K){
        aR=*(const float2*)(aP+k0+8);
        wR=*(const float4*)(wP+(long long)(k0+8)*NO);
      }
      #pragma unroll
      for(int kk=0;kk<8;kk++){
        const u64* wp=(const u64*)&Ws[kk][tcol];
        u64 b0=wp[0],b1=wp[1],b2=wp[2],b3=wp[3];
        #pragma unroll
        for(int i=0;i<4;i++){
          u64 a2=As2[kk][trow+i];
          acc[i][0]=ffma2(a2,b0,acc[i][0]);
          acc[i][1]=ffma2(a2,b1,acc[i][1]);
          acc[i][2]=ffma2(a2,b2,acc[i][2]);
          acc[i][3]=ffma2(a2,b3,acc[i][3]);
        }
      }
    }
  }
  const float* bp=bias+(long long)n*sbn+col0+tcol;
  float4 bv0=*(const float4*)bp, bv1=*(const float4*)(bp+4);
  #pragma unroll
  for(int i=0;i<4;i++){
    float* cp=C+((long long)n*B+row0+trow+i)*NO+col0+tcol;
    float2 p0=upk2(acc[i][0]),p1=upk2(acc[i][1]),p2=upk2(acc[i][2]),p3=upk2(acc[i][3]);
    *(float4*)cp    =make_float4(p0.x+bv0.x,p0.y+bv0.y,p1.x+bv0.z,p1.y+bv0.w);
    *(float4*)(cp+4)=make_float4(p2.x+bv1.x,p2.y+bv1.y,p3.x+bv1.z,p3.y+bv1.w);
  }
}

// G-mix of gates + LSTM pointwise. One CTA per batch element.
__global__ __launch_bounds__(128) void mix_lstm(
  const float* __restrict__ gates, const float* __restrict__ G,
  float* __restrict__ h, float* __restrict__ c, float* __restrict__ yi)
{
  const int b=blockIdx.x, k=threadIdx.x;
  __shared__ float Gs[NN*NN];
  __shared__ float sg[NN][256];
  for(int i=k;i<NN*NN;i+=128) Gs[i]=G[i];
  // phase A: i-gate [0,128) -> sg[n][0..127], g-gate [256,384) -> sg[n][128..255]
  for(int tt=0;tt<12;tt++){
    int id=k+tt*128, n=id>>6, r=id&63;
    int o=(r<32)?(r*4):(256+(r-32)*4);
    *(float4*)&sg[n][r*4]=*(const float4*)&gates[((long long)n*B+b)*G4+o];
  }
  __syncthreads();
  float acc_i[NN],acc_g[NN];
  #pragma unroll
  for(int m=0;m<NN;m++){acc_i[m]=0.f;acc_g[m]=0.f;}
  #pragma unroll 1
  for(int n=0;n<NN;n++){
    float gi=sg[n][k], gg=sg[n][128+k];
    #pragma unroll
    for(int m=0;m<NN;m++){
      float gmn=Gs[m*NN+n];
      acc_i[m]+=gmn*gi; acc_g[m]+=gmn*gg;
    }
  }
  float tmp[NN];
  #pragma unroll
  for(int m=0;m<NN;m++) tmp[m]=sigf(acc_i[m])*tanhf(acc_g[m]);
  __syncthreads();
  // phase B: f-gate [128,256), o-gate [384,512)
  for(int tt=0;tt<12;tt++){
    int id=k+tt*128, n=id>>6, r=id&63;
    int o=(r<32)?(128+r*4):(384+(r-32)*4);
    *(float4*)&sg[n][r*4]=*(const float4*)&gates[((long long)n*B+b)*G4+o];
  }
  __syncthreads();
  float acc_f[NN],acc_o[NN];
  #pragma unroll
  for(int m=0;m<NN;m++){acc_f[m]=0.f;acc_o[m]=0.f;}
  #pragma unroll 1
  for(int n=0;n<NN;n++){
    float gf=sg[n][k], go=sg[n][128+k];
    #pragma unroll
    for(int m=0;m<NN;m++){
      float gmn=Gs[m*NN+n];
      acc_f[m]+=gmn*gf; acc_o[m]+=gmn*go;
    }
  }
  #pragma unroll 1
  for(int m=0;m<NN;m++){
    long long idx=((long long)m*B+b)*OUTF+k;
    float cn=sigf(acc_f[m])*c[idx]+tmp[m];
    float hh=sigf(acc_o[m])*tanhf(cn);
    c[idx]=cn; h[idx]=hh;
    if(yi) yi[idx]=tanhf(hh);
  }
}

// initial state: mix h0/c0 pre-activations, build xi0 and loc_start
__global__ __launch_bounds__(128) void init_mix(
  const float* __restrict__ t1, const float* __restrict__ t2,
  const float* __restrict__ G, const float* __restrict__ x, const float* __restrict__ z)
{
  const int b=blockIdx.x, k=threadIdx.x;
  __shared__ float Gs[NN*NN];
  __shared__ float s1[NN][OUTF], s2[NN][OUTF];
  for(int i=k;i<NN*NN;i+=128) Gs[i]=G[i];
  for(int tt=0;tt<6;tt++){
    int id=k+tt*128, n=id>>5, r=(id&31)*4;
    *(float4*)&s1[n][r]=*(const float4*)&t1[((long long)n*B+b)*OUTF+r];
    *(float4*)&s2[n][r]=*(const float4*)&t2[((long long)n*B+b)*OUTF+r];
  }
  __syncthreads();
  #pragma unroll 1
  for(int m=0;m<NN;m++){
    float hh=0.f, cc=0.f;
    for(int n=0;n<NN;n++){
      float gmn=Gs[m*NN+n];
      hh+=gmn*s1[n][k]; cc+=gmn*s2[n][k];
    }
    long long idx=((long long)m*B+b)*OUTF+k;
    g_h1[idx]=hh; g_h2[idx]=hh; g_c1[idx]=cc; g_c2[idx]=cc;
  }
  for(int id=k;id<NN*K0;id+=128){
    int n=id/K0, f=id%K0;
    float v=(f<64)? z[((long long)b*NN+n)*64+f] : x[((long long)b*NN+n)*8+(f-64)];
    g_xi[((long long)n*B+b)*K0+f]=v;
  }
  for(int id=k;id<NN*4;id+=128){
    int n=id>>2, j=id&3;
    g_ls[((long long)n*B+b)*4+j]=x[((long long)b*NN+n)*8+j];
  }
}

// per-step tail: mix+tanh of fc outputs, loc/logz projections, second mix,
// quaternion normalize+multiply, outputs, xi update. One CTA per batch element.
__global__ __launch_bounds__(256) void tail_step(
  int t, const float* __restrict__ t1, const float* __restrict__ t2,
  const float* __restrict__ G,
  const float* __restrict__ locW, const float* __restrict__ locb,
  const float* __restrict__ logzW, const float* __restrict__ logzb,
  float* __restrict__ out)
{
  const int b=blockIdx.x, tid=threadIdx.x;
  __shared__ float Gs[NN*NN];
  __shared__ float s1[NN][OUTF], s2[NN][OUTF];
  __shared__ float q1[NN][4], q2[NN][4];
  for(int i=tid;i<NN*NN;i+=256) Gs[i]=G[i];
  for(int tt=0;tt<3;tt++){
    int id=tid+tt*256, n=id>>5, r=(id&31)*4;
    *(float4*)&s1[n][r]=*(const float4*)&t1[((long long)n*B+b)*OUTF+r];
    *(float4*)&s2[n][r]=*(const float4*)&t2[((long long)n*B+b)*OUTF+r];
  }
  __syncthreads();
  float y1r[12], y2r[12];
  #pragma unroll
  for(int e=0;e<12;e++){
    int id=tid+e*256, m=id>>7, k=id&127;
    float a1=0.f,a2=0.f;
    for(int n=0;n<NN;n++){
      float gmn=Gs[m*NN+n];
      a1+=gmn*s1[n][k]; a2+=gmn*s2[n][k];
    }
    y1r[e]=tanhf(a1); y2r[e]=tanhf(a2);
  }
  __syncthreads();
  #pragma unroll
  for(int e=0;e<12;e++){
    int id=tid+e*256, m=id>>7, k=id&127;
    s1[m][k]=y1r[e]; s2[m][k]=y2r[e];
  }
  __syncthreads();
  if(tid<72){
    int m=tid/3, j=tid-3*(tid/3);
    float s=locb[j];
    for(int k2=0;k2<OUTF;k2++) s+=s1[m][k2]*locW[k2*3+j];
    q1[m][j]=s;
  } else if(tid<168){
    int u=tid-72, m=u>>2, j=u&3;
    float s=logzb[j];
    for(int k2=0;k2<OUTF;k2++) s+=s2[m][k2]*logzW[k2*4+j];
    q2[m][j]=s;
  }
  __syncthreads();
  if(tid<NN){
    int m=tid;
    float l0=0.f,l1=0.f,l2=0.f,z0=0.f,z1=0.f,z2=0.f,z3=0.f;
    for(int n=0;n<NN;n++){
      float gmn=Gs[m*NN+n];
      l0+=gmn*q1[n][0]; l1+=gmn*q1[n][1]; l2+=gmn*q1[n][2];
      z0+=gmn*q2[n][0]; z1+=gmn*q2[n][1]; z2+=gmn*q2[n][2]; z3+=gmn*q2[n][3];
    }
    float rn=rsqrtf(1.f+l0*l0+l1*l1+l2*l2);
    float dw=rn, dx=l0*rn, dy=l1*rn, dz=l2*rn;
    float4 ls=*(const float4*)&g_ls[((long long)m*B+b)*4];
    float qw=ls.x*dw - ls.y*dx - ls.z*dy - ls.w*dz;
    float qx=ls.x*dx + ls.y*dw + ls.z*dz - ls.w*dy;
    float qy=ls.x*dy - ls.y*dz + ls.z*dw + ls.w*dx;
    float qz=ls.x*dz + ls.y*dy - ls.z*dx + ls.w*dw;
    *(float4*)&g_ls[((long long)m*B+b)*4]=make_float4(qw,qx,qy,qz);
    long long ob=(((long long)b*T+t)*NN+m)*4;
    out[ob+0]=qw; out[ob+1]=qx; out[ob+2]=qy; out[ob+3]=qz;
    long long oz=(long long)B*T*NN*4+ob;
    out[oz+0]=z0; out[oz+1]=z1; out[oz+2]=z2; out[oz+3]=z3;
    float* xp=&g_xi[((long long)m*B+b)*K0+64];
    xp[0]=qw; xp[1]=qx; xp[2]=qy; xp[3]=qz;
    xp[4]=dw; xp[5]=dx; xp[6]=dy; xp[7]=dz;
  }
}

extern "C" void kernel_launch(void* const* d_in, const int* in_sizes, int n_in,
                              void* d_out, int out_size){
  const float* x    =(const float*)d_in[0];
  const float* enc  =(const float*)d_in[1];
  const float* z    =(const float*)d_in[2];
  const float* G    =(const float*)d_in[4];
  const float* Wx0  =(const float*)d_in[5];
  const float* Wh0  =(const float*)d_in[6];
  const float* b0   =(const float*)d_in[7];
  const float* Wx1  =(const float*)d_in[8];
  const float* Wh1  =(const float*)d_in[9];
  const float* b1   =(const float*)d_in[10];
  const float* fcW  =(const float*)d_in[11];
  const float* fcb  =(const float*)d_in[12];
  const float* fc2W =(const float*)d_in[13];
  const float* fc2b =(const float*)d_in[14];
  const float* ih1W =(const float*)d_in[15];
  const float* ih1b =(const float*)d_in[16];
  const float* ih2W =(const float*)d_in[17];
  const float* ih2b =(const float*)d_in[18];
  const float* locW =(const float*)d_in[19];
  const float* locb =(const float*)d_in[20];
  const float* logzW=(const float*)d_in[21];
  const float* logzb=(const float*)d_in[22];
  float* out=(float*)d_out;

  float *t1p,*t2p,*gp,*xip,*h1p,*c1p,*h2p,*c2p,*yip;
  cudaGetSymbolAddress((void**)&t1p, g_t1);
  cudaGetSymbolAddress((void**)&t2p, g_t2);
  cudaGetSymbolAddress((void**)&gp,  g_gates);
  cudaGetSymbolAddress((void**)&xip, g_xi);
  cudaGetSymbolAddress((void**)&h1p, g_h1);
  cudaGetSymbolAddress((void**)&c1p, g_c1);
  cudaGetSymbolAddress((void**)&h2p, g_h2);
  cudaGetSymbolAddress((void**)&c2p, g_c2);
  cudaGetSymbolAddress((void**)&yip, g_yi);

  // init: h0/c0 pre-activations (weights shared across nodes -> node stride 0)
  gemm_dual<<<dim3(1,8,NN),256>>>(enc,256,NN*256,256, ih1W,0,
                                  nullptr,0,0,0, nullptr,0, ih1b,0, t1p,128);
  gemm_dual<<<dim3(1,8,NN),256>>>(enc,256,NN*256,256, ih2W,0,
                                  nullptr,0,0,0, nullptr,0, ih2b,0, t2p,128);
  init_mix<<<B,128>>>(t1p,t2p,G,x,z);

  for(int t=0;t<T;t++){
    gemm_dual<<<dim3(4,8,NN),256>>>(xip,(long long)B*K0,K0,K0, Wx0,(long long)K0*G4,
                                    h1p,(long long)B*OUTF,OUTF,OUTF, Wh0,(long long)OUTF*G4,
                                    b0,G4, gp,G4);
    mix_lstm<<<B,128>>>(gp,G,h1p,c1p,nullptr);
    gemm_dual<<<dim3(4,8,NN),256>>>(h1p,(long long)B*OUTF,OUTF,OUTF, Wx1,(long long)OUTF*G4,
                                    h2p,(long long)B*OUTF,OUTF,OUTF, Wh1,(long long)OUTF*G4,
                                    b1,G4, gp,G4);
    mix_lstm<<<B,128>>>(gp,G,h2p,c2p,yip);
    gemm_dual<<<dim3(1,8,NN),256>>>(yip,(long long)B*OUTF,OUTF,OUTF, fcW,(long long)OUTF*OUTF,
                                    nullptr,0,0,0, nullptr,0, fcb,OUTF, t1p,OUTF);
    gemm_dual<<<dim3(1,8,NN),256>>>(yip,(long long)B*OUTF,OUTF,OUTF, fc2W,(long long)OUTF*OUTF,
                                    nullptr,0,0,0, nullptr,0, fc2b,OUTF, t2p,OUTF);
    tail_step<<<B,256>>>(t,t1p,t2p,G,locW,locb,logzW,logzb,out);
  }
}

// round 5
// speedup vs baseline: 1.5816x; 1.5816x over previous
#include <cuda_runtime.h>
#include <math.h>

#define B 512
#define NN 24
#define T 25
#define OUTF 128
#define G4 512
#define K0 72

__device__ float g_xi[NN*B*K0];
__device__ float g_h1[NN*B*OUTF];
__device__ float g_c1[NN*B*OUTF];
__device__ float g_h2[NN*B*OUTF];
__device__ float g_c2[NN*B*OUTF];
__device__ float g_yi[NN*B*OUTF];
__device__ float g_gates[NN*B*G4];
__device__ float g_t1[NN*B*OUTF];
__device__ float g_t2[NN*B*OUTF];
__device__ float g_ls[NN*B*4];

typedef unsigned long long u64;
__device__ __forceinline__ u64 ffma2(u64 a,u64 b,u64 c){u64 d;asm("fma.rn.f32x2 %0,%1,%2,%3;":"=l"(d):"l"(a),"l"(b),"l"(c));return d;}
__device__ __forceinline__ u64 pk2(float x,float y){u64 r;asm("mov.b64 %0,{%1,%2};":"=l"(r):"f"(x),"f"(y));return r;}
__device__ __forceinline__ float2 upk2(u64 v){float2 r;asm("mov.b64 {%0,%1},%2;":"=f"(r.x),"=f"(r.y):"l"(v));return r;}
__device__ __forceinline__ float sigf(float x){return 1.f/(1.f+expf(-x));}

// C[n][row][:NO] = bias[n] + A1[n,row,:K1]@W1[n] + A2[n,row,:K2]@W2[n]
// blockIdx.z >= nzA -> alternate (W1b, biasb, Cb) with same A1 (merged twin GEMMs).
// BM=64, BN=32*NPAIR, BK=8. 256 threads, 4x(2*NPAIR) micro-tile in f32x2 pairs.
// Thread (tid&15)=j owns column pairs {2j+32t}, conflict-free LDS.64 reads.
// All K must be multiples of 8 (72,128,256 all are).
template<int NPAIR>
__global__ __launch_bounds__(256,2) void gemm_np(
  const float* __restrict__ A1, long long sA1n, int sA1r, int K1,
  const float* __restrict__ W1, long long sW1n,
  const float* __restrict__ A2, long long sA2n, int sA2r, int K2,
  const float* __restrict__ W2, long long sW2n,
  const float* __restrict__ bias, int sbn,
  float* __restrict__ C, int NO, int nzA,
  const float* __restrict__ W1b, const float* __restrict__ biasb, float* __restrict__ Cb)
{
  constexpr int BN = 32*NPAIR;
  constexpr int WPT = BN/32;           // floats of W per thread per k-row
  int n = blockIdx.z;
  if(n >= nzA){ n -= nzA; W1 = W1b; bias = biasb; C = Cb; }
  const int row0 = blockIdx.y*64, col0 = blockIdx.x*BN;
  const int tid = threadIdx.x;
  const int jj = tid&15, trow = (tid>>4)*4;
  const int la_r = tid>>2, la_k = (tid&3)*2;
  const int lw_k = tid>>5, lw_c = (tid&31)*WPT;

  __shared__ float As[2][8][64];
  __shared__ float Ws[2][8][BN];

  u64 acc[4][NPAIR];
  #pragma unroll
  for(int i=0;i<4;i++){
    #pragma unroll
    for(int t=0;t<NPAIR;t++) acc[i][t]=0ull;
  }

  const int n1 = K1>>3, n2 = K2>>3, nt = n1+n2;
  const float* pA1 = A1 + (long long)n*sA1n + (long long)(row0+la_r)*sA1r + la_k;
  const float* pW1 = W1 + (long long)n*sW1n + (long long)lw_k*NO + col0 + lw_c;
  const float* pA2 = (K2>0) ? A2 + (long long)n*sA2n + (long long)(row0+la_r)*sA2r + la_k : pA1;
  const float* pW2 = (K2>0) ? W2 + (long long)n*sW2n + (long long)lw_k*NO + col0 + lw_c : pW1;

  float2 aR;
  float4 wRa, wRb;
  auto loadit = [&](int it){
    const float* ap; const float* wp;
    if(it < n1){ ap = pA1 + it*8;      wp = pW1 + (long long)it*8*NO; }
    else       { ap = pA2 + (it-n1)*8; wp = pW2 + (long long)(it-n1)*8*NO; }
    aR = *(const float2*)ap;
    wRa = *(const float4*)wp;
    if(NPAIR==8) wRb = *(const float4*)(wp+4);
  };
  loadit(0);

  int cur = 0;
  for(int it=0; it<nt; ++it){
    As[cur][la_k  ][la_r] = aR.x;
    As[cur][la_k+1][la_r] = aR.y;
    *(float4*)&Ws[cur][lw_k][lw_c] = wRa;
    if(NPAIR==8) *(float4*)&Ws[cur][lw_k][lw_c+4] = wRb;
    __syncthreads();
    if(it+1 < nt) loadit(it+1);
    #pragma unroll
    for(int kk=0;kk<8;kk++){
      float4 av = *(const float4*)&As[cur][kk][trow];
      u64 ad0 = pk2(av.x,av.x), ad1 = pk2(av.y,av.y);
      u64 ad2 = pk2(av.z,av.z), ad3 = pk2(av.w,av.w);
      u64 wv[NPAIR];
      #pragma unroll
      for(int t=0;t<NPAIR;t++) wv[t] = *(const u64*)&Ws[cur][kk][2*jj+32*t];
      #pragma unroll
      for(int t=0;t<NPAIR;t++){
        acc[0][t] = ffma2(ad0, wv[t], acc[0][t]);
        acc[1][t] = ffma2(ad1, wv[t], acc[1][t]);
        acc[2][t] = ffma2(ad2, wv[t], acc[2][t]);
        acc[3][t] = ffma2(ad3, wv[t], acc[3][t]);
      }
    }
    cur ^= 1;
  }

  const float* bp = bias + (long long)n*sbn + col0;
  #pragma unroll
  for(int t=0;t<NPAIR;t++){
    float2 bv = *(const float2*)&bp[2*jj+32*t];
    #pragma unroll
    for(int i=0;i<4;i++){
      float2 p = upk2(acc[i][t]);
      *(float2*)&C[((long long)n*B+row0+trow+i)*NO + col0 + 2*jj + 32*t]
        = make_float2(p.x+bv.x, p.y+bv.y);
    }
  }
}

// G-mix of gates + LSTM pointwise. One CTA per batch element.
__global__ __launch_bounds__(128) void mix_lstm(
  const float* __restrict__ gates, const float* __restrict__ G,
  float* __restrict__ h, float* __restrict__ c, float* __restrict__ yi)
{
  const int b=blockIdx.x, k=threadIdx.x;
  __shared__ float Gs[NN*NN];
  __shared__ float sg[NN][256];
  for(int i=k;i<NN*NN;i+=128) Gs[i]=G[i];
  for(int tt=0;tt<12;tt++){
    int id=k+tt*128, n=id>>6, r=id&63;
    int o=(r<32)?(r*4):(256+(r-32)*4);
    *(float4*)&sg[n][r*4]=*(const float4*)&gates[((long long)n*B+b)*G4+o];
  }
  __syncthreads();
  float acc_i[NN],acc_g[NN];
  #pragma unroll
  for(int m=0;m<NN;m++){acc_i[m]=0.f;acc_g[m]=0.f;}
  #pragma unroll 1
  for(int n=0;n<NN;n++){
    float gi=sg[n][k], gg=sg[n][128+k];
    #pragma unroll
    for(int m=0;m<NN;m++){
      float gmn=Gs[m*NN+n];
      acc_i[m]+=gmn*gi; acc_g[m]+=gmn*gg;
    }
  }
  float tmp[NN];
  #pragma unroll
  for(int m=0;m<NN;m++) tmp[m]=sigf(acc_i[m])*tanhf(acc_g[m]);
  __syncthreads();
  for(int tt=0;tt<12;tt++){
    int id=k+tt*128, n=id>>6, r=id&63;
    int o=(r<32)?(128+r*4):(384+(r-32)*4);
    *(float4*)&sg[n][r*4]=*(const float4*)&gates[((long long)n*B+b)*G4+o];
  }
  __syncthreads();
  float acc_f[NN],acc_o[NN];
  #pragma unroll
  for(int m=0;m<NN;m++){acc_f[m]=0.f;acc_o[m]=0.f;}
  #pragma unroll 1
  for(int n=0;n<NN;n++){
    float gf=sg[n][k], go=sg[n][128+k];
    #pragma unroll
    for(int m=0;m<NN;m++){
      float gmn=Gs[m*NN+n];
      acc_f[m]+=gmn*gf; acc_o[m]+=gmn*go;
    }
  }
  #pragma unroll 1
  for(int m=0;m<NN;m++){
    long long idx=((long long)m*B+b)*OUTF+k;
    float cn=sigf(acc_f[m])*c[idx]+tmp[m];
    float hh=sigf(acc_o[m])*tanhf(cn);
    c[idx]=cn; h[idx]=hh;
    if(yi) yi[idx]=tanhf(hh);
  }
}

// initial state: mix h0/c0 pre-activations, build xi0 and loc_start
__global__ __launch_bounds__(128) void init_mix(
  const float* __restrict__ t1, const float* __restrict__ t2,
  const float* __restrict__ G, const float* __restrict__ x, const float* __restrict__ z)
{
  const int b=blockIdx.x, k=threadIdx.x;
  __shared__ float Gs[NN*NN];
  __shared__ float s1[NN][OUTF], s2[NN][OUTF];
  for(int i=k;i<NN*NN;i+=128) Gs[i]=G[i];
  for(int tt=0;tt<6;tt++){
    int id=k+tt*128, n=id>>5, r=(id&31)*4;
    *(float4*)&s1[n][r]=*(const float4*)&t1[((long long)n*B+b)*OUTF+r];
    *(float4*)&s2[n][r]=*(const float4*)&t2[((long long)n*B+b)*OUTF+r];
  }
  __syncthreads();
  #pragma unroll 1
  for(int m=0;m<NN;m++){
    float hh=0.f, cc=0.f;
    for(int n=0;n<NN;n++){
      float gmn=Gs[m*NN+n];
      hh+=gmn*s1[n][k]; cc+=gmn*s2[n][k];
    }
    long long idx=((long long)m*B+b)*OUTF+k;
    g_h1[idx]=hh; g_h2[idx]=hh; g_c1[idx]=cc; g_c2[idx]=cc;
  }
  for(int id=k;id<NN*K0;id+=128){
    int n=id/K0, f=id%K0;
    float v=(f<64)? z[((long long)b*NN+n)*64+f] : x[((long long)b*NN+n)*8+(f-64)];
    g_xi[((long long)n*B+b)*K0+f]=v;
  }
  for(int id=k;id<NN*4;id+=128){
    int n=id>>2, j=id&3;
    g_ls[((long long)n*B+b)*4+j]=x[((long long)b*NN+n)*8+j];
  }
}

// per-step tail: mix+tanh of fc outputs, loc/logz projections, second mix,
// quaternion normalize+multiply, outputs, xi update. One CTA per batch element.
__global__ __launch_bounds__(256) void tail_step(
  int t, const float* __restrict__ t1, const float* __restrict__ t2,
  const float* __restrict__ G,
  const float* __restrict__ locW, const float* __restrict__ locb,
  const float* __restrict__ logzW, const float* __restrict__ logzb,
  float* __restrict__ out)
{
  const int b=blockIdx.x, tid=threadIdx.x;
  __shared__ float Gs[NN*NN];
  __shared__ float s1[NN][OUTF], s2[NN][OUTF];
  __shared__ float q1[NN][4], q2[NN][4];
  for(int i=tid;i<NN*NN;i+=256) Gs[i]=G[i];
  for(int tt=0;tt<3;tt++){
    int id=tid+tt*256, n=id>>5, r=(id&31)*4;
    *(float4*)&s1[n][r]=*(const float4*)&t1[((long long)n*B+b)*OUTF+r];
    *(float4*)&s2[n][r]=*(const float4*)&t2[((long long)n*B+b)*OUTF+r];
  }
  __syncthreads();
  float y1r[12], y2r[12];
  #pragma unroll
  for(int e=0;e<12;e++){
    int id=tid+e*256, m=id>>7, k=id&127;
    float a1=0.f,a2=0.f;
    for(int n=0;n<NN;n++){
      float gmn=Gs[m*NN+n];
      a1+=gmn*s1[n][k]; a2+=gmn*s2[n][k];
    }
    y1r[e]=tanhf(a1); y2r[e]=tanhf(a2);
  }
  __syncthreads();
  #pragma unroll
  for(int e=0;e<12;e++){
    int id=tid+e*256, m=id>>7, k=id&127;
    s1[m][k]=y1r[e]; s2[m][k]=y2r[e];
  }
  __syncthreads();
  if(tid<72){
    int m=tid/3, j=tid-3*(tid/3);
    float s=locb[j];
    for(int k2=0;k2<OUTF;k2++) s+=s1[m][k2]*locW[k2*3+j];
    q1[m][j]=s;
  } else if(tid<168){
    int u=tid-72, m=u>>2, j=u&3;
    float s=logzb[j];
    for(int k2=0;k2<OUTF;k2++) s+=s2[m][k2]*logzW[k2*4+j];
    q2[m][j]=s;
  }
  __syncthreads();
  if(tid<NN){
    int m=tid;
    float l0=0.f,l1=0.f,l2=0.f,z0=0.f,z1=0.f,z2=0.f,z3=0.f;
    for(int n=0;n<NN;n++){
      float gmn=Gs[m*NN+n];
      l0+=gmn*q1[n][0]; l1+=gmn*q1[n][1]; l2+=gmn*q1[n][2];
      z0+=gmn*q2[n][0]; z1+=gmn*q2[n][1]; z2+=gmn*q2[n][2]; z3+=gmn*q2[n][3];
    }
    float rn=rsqrtf(1.f+l0*l0+l1*l1+l2*l2);
    float dw=rn, dx=l0*rn, dy=l1*rn, dz=l2*rn;
    float4 ls=*(const float4*)&g_ls[((long long)m*B+b)*4];
    float qw=ls.x*dw - ls.y*dx - ls.z*dy - ls.w*dz;
    float qx=ls.x*dx + ls.y*dw + ls.z*dz - ls.w*dy;
    float qy=ls.x*dy - ls.y*dz + ls.z*dw + ls.w*dx;
    float qz=ls.x*dz + ls.y*dy - ls.z*dx + ls.w*dw;
    *(float4*)&g_ls[((long long)m*B+b)*4]=make_float4(qw,qx,qy,qz);
    long long ob=(((long long)b*T+t)*NN+m)*4;
    out[ob+0]=qw; out[ob+1]=qx; out[ob+2]=qy; out[ob+3]=qz;
    long long oz=(long long)B*T*NN*4+ob;
    out[oz+0]=z0; out[oz+1]=z1; out[oz+2]=z2; out[oz+3]=z3;
    float* xp=&g_xi[((long long)m*B+b)*K0+64];
    xp[0]=qw; xp[1]=qx; xp[2]=qy; xp[3]=qz;
    xp[4]=dw; xp[5]=dx; xp[6]=dy; xp[7]=dz;
  }
}

extern "C" void kernel_launch(void* const* d_in, const int* in_sizes, int n_in,
                              void* d_out, int out_size){
  const float* x    =(const float*)d_in[0];
  const float* enc  =(const float*)d_in[1];
  const float* z    =(const float*)d_in[2];
  const float* G    =(const float*)d_in[4];
  const float* Wx0  =(const float*)d_in[5];
  const float* Wh0  =(const float*)d_in[6];
  const float* b0   =(const float*)d_in[7];
  const float* Wx1  =(const float*)d_in[8];
  const float* Wh1  =(const float*)d_in[9];
  const float* b1   =(const float*)d_in[10];
  const float* fcW  =(const float*)d_in[11];
  const float* fcb  =(const float*)d_in[12];
  const float* fc2W =(const float*)d_in[13];
  const float* fc2b =(const float*)d_in[14];
  const float* ih1W =(const float*)d_in[15];
  const float* ih1b =(const float*)d_in[16];
  const float* ih2W =(const float*)d_in[17];
  const float* ih2b =(const float*)d_in[18];
  const float* locW =(const float*)d_in[19];
  const float* locb =(const float*)d_in[20];
  const float* logzW=(const float*)d_in[21];
  const float* logzb=(const float*)d_in[22];
  float* out=(float*)d_out;

  float *t1p,*t2p,*gp,*xip,*h1p,*c1p,*h2p,*c2p,*yip;
  cudaGetSymbolAddress((void**)&t1p, g_t1);
  cudaGetSymbolAddress((void**)&t2p, g_t2);
  cudaGetSymbolAddress((void**)&gp,  g_gates);
  cudaGetSymbolAddress((void**)&xip, g_xi);
  cudaGetSymbolAddress((void**)&h1p, g_h1);
  cudaGetSymbolAddress((void**)&c1p, g_c1);
  cudaGetSymbolAddress((void**)&h2p, g_h2);
  cudaGetSymbolAddress((void**)&c2p, g_c2);
  cudaGetSymbolAddress((void**)&yip, g_yi);

  // merged h0/c0 pre-activations (weights shared across nodes -> node stride 0)
  gemm_np<4><<<dim3(1,8,48),256>>>(enc,256,NN*256,256, ih1W,0,
                                   nullptr,0,0,0, nullptr,0, ih1b,0, t1p,128,
                                   24, ih2W, ih2b, t2p);
  init_mix<<<B,128>>>(t1p,t2p,G,x,z);

  for(int t=0;t<T;t++){
    gemm_np<8><<<dim3(2,8,24),256>>>(xip,(long long)B*K0,K0,K0, Wx0,(long long)K0*G4,
                                     h1p,(long long)B*OUTF,OUTF,OUTF, Wh0,(long long)OUTF*G4,
                                     b0,G4, gp,G4, 24, nullptr,nullptr,nullptr);
    mix_lstm<<<B,128>>>(gp,G,h1p,c1p,nullptr);
    gemm_np<8><<<dim3(2,8,24),256>>>(h1p,(long long)B*OUTF,OUTF,OUTF, Wx1,(long long)OUTF*G4,
                                     h2p,(long long)B*OUTF,OUTF,OUTF, Wh1,(long long)OUTF*G4,
                                     b1,G4, gp,G4, 24, nullptr,nullptr,nullptr);
    mix_lstm<<<B,128>>>(gp,G,h2p,c2p,yip);
    gemm_np<4><<<dim3(1,8,48),256>>>(yip,(long long)B*OUTF,OUTF,OUTF, fcW,(long long)OUTF*OUTF,
                                     nullptr,0,0,0, nullptr,0, fcb,OUTF, t1p,OUTF,
                                     24, fc2W, fc2b, t2p);
    tail_step<<<B,256>>>(t,t1p,t2p,G,locW,locb,logzW,logzb,out);
  }
}

// round 6
// speedup vs baseline: 1.6340x; 1.0332x over previous
#include <cuda_runtime.h>
#include <math.h>

#define B 512
#define NN 24
#define T 25
#define OUTF 128
#define G4 512
#define K0 72

__device__ float g_xi[NN*B*K0];
__device__ float g_h1[NN*B*OUTF];
__device__ float g_c1[NN*B*OUTF];
__device__ float g_h2[NN*B*OUTF];
__device__ float g_c2[NN*B*OUTF];
__device__ float g_yi[NN*B*OUTF];
__device__ float g_gates[NN*B*G4];
__device__ float g_t1[NN*B*OUTF];
__device__ float g_t2[NN*B*OUTF];
__device__ float g_ls[NN*B*4];

typedef unsigned long long u64;
__device__ __forceinline__ u64 ffma2(u64 a,u64 b,u64 c){u64 d;asm("fma.rn.f32x2 %0,%1,%2,%3;":"=l"(d):"l"(a),"l"(b),"l"(c));return d;}
__device__ __forceinline__ u64 pk2(float x,float y){u64 r;asm("mov.b64 %0,{%1,%2};":"=l"(r):"f"(x),"f"(y));return r;}
__device__ __forceinline__ float2 upk2(u64 v){float2 r;asm("mov.b64 {%0,%1},%2;":"=f"(r.x),"=f"(r.y):"l"(v));return r;}
__device__ __forceinline__ float sigf(float x){return 1.f/(1.f+expf(-x));}

// C[n][row][:NO] = bias[n] + A1[n,row,:K1]@W1[n] + A2[n,row,:K2]@W2[n]
// blockIdx.z >= nzA -> alternate (W1b, biasb, Cb) with same A1 (merged twin GEMMs).
template<int NPAIR>
__global__ __launch_bounds__(256,2) void gemm_np(
  const float* __restrict__ A1, long long sA1n, int sA1r, int K1,
  const float* __restrict__ W1, long long sW1n,
  const float* __restrict__ A2, long long sA2n, int sA2r, int K2,
  const float* __restrict__ W2, long long sW2n,
  const float* __restrict__ bias, int sbn,
  float* __restrict__ C, int NO, int nzA,
  const float* __restrict__ W1b, const float* __restrict__ biasb, float* __restrict__ Cb)
{
  constexpr int BN = 32*NPAIR;
  constexpr int WPT = BN/32;
  int n = blockIdx.z;
  if(n >= nzA){ n -= nzA; W1 = W1b; bias = biasb; C = Cb; }
  const int row0 = blockIdx.y*64, col0 = blockIdx.x*BN;
  const int tid = threadIdx.x;
  const int jj = tid&15, trow = (tid>>4)*4;
  const int la_r = tid>>2, la_k = (tid&3)*2;
  const int lw_k = tid>>5, lw_c = (tid&31)*WPT;

  __shared__ float As[2][8][64];
  __shared__ float Ws[2][8][BN];

  u64 acc[4][NPAIR];
  #pragma unroll
  for(int i=0;i<4;i++){
    #pragma unroll
    for(int t=0;t<NPAIR;t++) acc[i][t]=0ull;
  }

  const int n1 = K1>>3, n2 = K2>>3, nt = n1+n2;
  const float* pA1 = A1 + (long long)n*sA1n + (long long)(row0+la_r)*sA1r + la_k;
  const float* pW1 = W1 + (long long)n*sW1n + (long long)lw_k*NO + col0 + lw_c;
  const float* pA2 = (K2>0) ? A2 + (long long)n*sA2n + (long long)(row0+la_r)*sA2r + la_k : pA1;
  const float* pW2 = (K2>0) ? W2 + (long long)n*sW2n + (long long)lw_k*NO + col0 + lw_c : pW1;

  float2 aR;
  float4 wRa, wRb;
  auto loadit = [&](int it){
    const float* ap; const float* wp;
    if(it < n1){ ap = pA1 + it*8;      wp = pW1 + (long long)it*8*NO; }
    else       { ap = pA2 + (it-n1)*8; wp = pW2 + (long long)(it-n1)*8*NO; }
    aR = *(const float2*)ap;
    wRa = *(const float4*)wp;
    if(NPAIR==8) wRb = *(const float4*)(wp+4);
  };
  loadit(0);

  int cur = 0;
  for(int it=0; it<nt; ++it){
    As[cur][la_k  ][la_r] = aR.x;
    As[cur][la_k+1][la_r] = aR.y;
    *(float4*)&Ws[cur][lw_k][lw_c] = wRa;
    if(NPAIR==8) *(float4*)&Ws[cur][lw_k][lw_c+4] = wRb;
    __syncthreads();
    if(it+1 < nt) loadit(it+1);
    #pragma unroll
    for(int kk=0;kk<8;kk++){
      float4 av = *(const float4*)&As[cur][kk][trow];
      u64 ad0 = pk2(av.x,av.x), ad1 = pk2(av.y,av.y);
      u64 ad2 = pk2(av.z,av.z), ad3 = pk2(av.w,av.w);
      u64 wv[NPAIR];
      #pragma unroll
      for(int t=0;t<NPAIR;t++) wv[t] = *(const u64*)&Ws[cur][kk][2*jj+32*t];
      #pragma unroll
      for(int t=0;t<NPAIR;t++){
        acc[0][t] = ffma2(ad0, wv[t], acc[0][t]);
        acc[1][t] = ffma2(ad1, wv[t], acc[1][t]);
        acc[2][t] = ffma2(ad2, wv[t], acc[2][t]);
        acc[3][t] = ffma2(ad3, wv[t], acc[3][t]);
      }
    }
    cur ^= 1;
  }

  const float* bp = bias + (long long)n*sbn + col0;
  #pragma unroll
  for(int t=0;t<NPAIR;t++){
    float2 bv = *(const float2*)&bp[2*jj+32*t];
    #pragma unroll
    for(int i=0;i<4;i++){
      float2 p = upk2(acc[i][t]);
      *(float2*)&C[((long long)n*B+row0+trow+i)*NO + col0 + 2*jj + 32*t]
        = make_float2(p.x+bv.x, p.y+bv.y);
    }
  }
}

// G-mix of gates + LSTM pointwise. One CTA (256 threads) per batch element.
// half0 computes (i,g) gates -> stmp; half1 computes (f,o) -> sf/so.
// Update is split 12 m's per thread across all 256 threads.
__global__ __launch_bounds__(256) void mix_lstm(
  const float* __restrict__ gates, const float* __restrict__ G,
  float* __restrict__ h, float* __restrict__ c, float* __restrict__ yi)
{
  const int b=blockIdx.x, tid=threadIdx.x;
  const int k = tid&127, half = tid>>7;
  __shared__ float Gs[NN*NN];
  __shared__ float stmp[NN][128];
  __shared__ float sf[NN][128];
  __shared__ float so[NN][128];
  for(int i=tid;i<NN*NN;i+=256) Gs[i]=G[i];
  __syncthreads();
  float a0[NN], a1[NN];
  #pragma unroll
  for(int m=0;m<NN;m++){a0[m]=0.f;a1[m]=0.f;}
  const float* gb0 = gates + (long long)b*G4 + k + (half?128:0);
  const float* gb1 = gates + (long long)b*G4 + k + (half?384:256);
  #pragma unroll 2
  for(int n=0;n<NN;n++){
    float ga = gb0[(long long)n*B*G4];
    float gg = gb1[(long long)n*B*G4];
    #pragma unroll
    for(int m=0;m<NN;m++){
      float gmn=Gs[m*NN+n];
      a0[m]+=gmn*ga; a1[m]+=gmn*gg;
    }
  }
  if(half==0){
    #pragma unroll
    for(int m=0;m<NN;m++) stmp[m][k]=sigf(a0[m])*tanhf(a1[m]);
  }else{
    #pragma unroll
    for(int m=0;m<NN;m++){ sf[m][k]=a0[m]; so[m][k]=a1[m]; }
  }
  __syncthreads();
  const int m0 = half*12;
  #pragma unroll 1
  for(int mm=0;mm<12;mm++){
    int m = m0+mm;
    long long idx=((long long)m*B+b)*OUTF+k;
    float cn=sigf(sf[m][k])*c[idx]+stmp[m][k];
    float hh=sigf(so[m][k])*tanhf(cn);
    c[idx]=cn; h[idx]=hh;
    if(yi) yi[idx]=tanhf(hh);
  }
}

// initial state: mix h0/c0 pre-activations, build xi0 and loc_start
__global__ __launch_bounds__(128) void init_mix(
  const float* __restrict__ t1, const float* __restrict__ t2,
  const float* __restrict__ G, const float* __restrict__ x, const float* __restrict__ z)
{
  const int b=blockIdx.x, k=threadIdx.x;
  __shared__ float Gs[NN*NN];
  __shared__ float s1[NN][OUTF], s2[NN][OUTF];
  for(int i=k;i<NN*NN;i+=128) Gs[i]=G[i];
  for(int tt=0;tt<6;tt++){
    int id=k+tt*128, n=id>>5, r=(id&31)*4;
    *(float4*)&s1[n][r]=*(const float4*)&t1[((long long)n*B+b)*OUTF+r];
    *(float4*)&s2[n][r]=*(const float4*)&t2[((long long)n*B+b)*OUTF+r];
  }
  __syncthreads();
  #pragma unroll 1
  for(int m=0;m<NN;m++){
    float hh=0.f, cc=0.f;
    for(int n=0;n<NN;n++){
      float gmn=Gs[m*NN+n];
      hh+=gmn*s1[n][k]; cc+=gmn*s2[n][k];
    }
    long long idx=((long long)m*B+b)*OUTF+k;
    g_h1[idx]=hh; g_h2[idx]=hh; g_c1[idx]=cc; g_c2[idx]=cc;
  }
  for(int id=k;id<NN*K0;id+=128){
    int n=id/K0, f=id%K0;
    float v=(f<64)? z[((long long)b*NN+n)*64+f] : x[((long long)b*NN+n)*8+(f-64)];
    g_xi[((long long)n*B+b)*K0+f]=v;
  }
  for(int id=k;id<NN*4;id+=128){
    int n=id>>2, j=id&3;
    g_ls[((long long)n*B+b)*4+j]=x[((long long)b*NN+n)*8+j];
  }
}

// per-step tail: mix+tanh of fc outputs (half-split, direct loads), warp-reduced
// loc/logz projections, second mix, quaternion chain, outputs, xi update.
__global__ __launch_bounds__(256) void tail_step(
  int t, const float* __restrict__ t1, const float* __restrict__ t2,
  const float* __restrict__ G,
  const float* __restrict__ locW, const float* __restrict__ locb,
  const float* __restrict__ logzW, const float* __restrict__ logzb,
  float* __restrict__ out)
{
  const int b=blockIdx.x, tid=threadIdx.x;
  const int k = tid&127, half = tid>>7;
  __shared__ float Gs[NN*NN];
  __shared__ float sy1[NN][128], sy2[NN][128];
  __shared__ float sw[7][128];
  __shared__ float q1[NN][4], q2[NN][4];
  for(int i=tid;i<NN*NN;i+=256) Gs[i]=G[i];
  for(int i=tid;i<7*128;i+=256){
    int j=i>>7, kk=i&127;
    sw[j][kk] = (j<3) ? locW[kk*3+j] : logzW[kk*4+(j-3)];
  }
  __syncthreads();
  {
    float a[NN];
    #pragma unroll
    for(int m=0;m<NN;m++) a[m]=0.f;
    const float* tp = (half? t2 : t1) + (long long)b*OUTF + k;
    #pragma unroll 2
    for(int n=0;n<NN;n++){
      float v = tp[(long long)n*B*OUTF];
      #pragma unroll
      for(int m=0;m<NN;m++) a[m]+=Gs[m*NN+n]*v;
    }
    if(half==0){
      #pragma unroll
      for(int m=0;m<NN;m++) sy1[m][k]=tanhf(a[m]);
    }else{
      #pragma unroll
      for(int m=0;m<NN;m++) sy2[m][k]=tanhf(a[m]);
    }
  }
  __syncthreads();
  // 168 projection tasks (24 m x 7 j), 8 warps x 21 tasks, warp-reduced
  {
    const int w = tid>>5, l = tid&31;
    #pragma unroll 1
    for(int i=0;i<21;i++){
      int tt = w*21+i;
      int m = tt/7, j = tt%7;
      const float* src = (j<3)? sy1[m] : sy2[m];
      float s0 = src[l]*sw[j][l] + src[l+64]*sw[j][l+64];
      float s1v= src[l+32]*sw[j][l+32] + src[l+96]*sw[j][l+96];
      float s = s0+s1v;
      #pragma unroll
      for(int o=16;o;o>>=1) s += __shfl_xor_sync(0xffffffffu,s,o);
      if(l==0){
        if(j<3) q1[m][j]=s+locb[j];
        else    q2[m][j-3]=s+logzb[j-3];
      }
    }
  }
  __syncthreads();
  if(tid<NN){
    int m=tid;
    float l0=0.f,l1=0.f,l2=0.f,z0=0.f,z1=0.f,z2=0.f,z3=0.f;
    for(int n=0;n<NN;n++){
      float gmn=Gs[m*NN+n];
      l0+=gmn*q1[n][0]; l1+=gmn*q1[n][1]; l2+=gmn*q1[n][2];
      z0+=gmn*q2[n][0]; z1+=gmn*q2[n][1]; z2+=gmn*q2[n][2]; z3+=gmn*q2[n][3];
    }
    float rn=rsqrtf(1.f+l0*l0+l1*l1+l2*l2);
    float dw=rn, dx=l0*rn, dy=l1*rn, dz=l2*rn;
    float4 ls=*(const float4*)&g_ls[((long long)m*B+b)*4];
    float qw=ls.x*dw - ls.y*dx - ls.z*dy - ls.w*dz;
    float qx=ls.x*dx + ls.y*dw + ls.z*dz - ls.w*dy;
    float qy=ls.x*dy - ls.y*dz + ls.z*dw + ls.w*dx;
    float qz=ls.x*dz + ls.y*dy - ls.z*dx + ls.w*dw;
    *(float4*)&g_ls[((long long)m*B+b)*4]=make_float4(qw,qx,qy,qz);
    long long ob=(((long long)b*T+t)*NN+m)*4;
    out[ob+0]=qw; out[ob+1]=qx; out[ob+2]=qy; out[ob+3]=qz;
    long long oz=(long long)B*T*NN*4+ob;
    out[oz+0]=z0; out[oz+1]=z1; out[oz+2]=z2; out[oz+3]=z3;
    float* xp=&g_xi[((long long)m*B+b)*K0+64];
    xp[0]=qw; xp[1]=qx; xp[2]=qy; xp[3]=qz;
    xp[4]=dw; xp[5]=dx; xp[6]=dy; xp[7]=dz;
  }
}

extern "C" void kernel_launch(void* const* d_in, const int* in_sizes, int n_in,
                              void* d_out, int out_size){
  const float* x    =(const float*)d_in[0];
  const float* enc  =(const float*)d_in[1];
  const float* z    =(const float*)d_in[2];
  const float* G    =(const float*)d_in[4];
  const float* Wx0  =(const float*)d_in[5];
  const float* Wh0  =(const float*)d_in[6];
  const float* b0   =(const float*)d_in[7];
  const float* Wx1  =(const float*)d_in[8];
  const float* Wh1  =(const float*)d_in[9];
  const float* b1   =(const float*)d_in[10];
  const float* fcW  =(const float*)d_in[11];
  const float* fcb  =(const float*)d_in[12];
  const float* fc2W =(const float*)d_in[13];
  const float* fc2b =(const float*)d_in[14];
  const float* ih1W =(const float*)d_in[15];
  const float* ih1b =(const float*)d_in[16];
  const float* ih2W =(const float*)d_in[17];
  const float* ih2b =(const float*)d_in[18];
  const float* locW =(const float*)d_in[19];
  const float* locb =(const float*)d_in[20];
  const float* logzW=(const float*)d_in[21];
  const float* logzb=(const float*)d_in[22];
  float* out=(float*)d_out;

  float *t1p,*t2p,*gp,*xip,*h1p,*c1p,*h2p,*c2p,*yip;
  cudaGetSymbolAddress((void**)&t1p, g_t1);
  cudaGetSymbolAddress((void**)&t2p, g_t2);
  cudaGetSymbolAddress((void**)&gp,  g_gates);
  cudaGetSymbolAddress((void**)&xip, g_xi);
  cudaGetSymbolAddress((void**)&h1p, g_h1);
  cudaGetSymbolAddress((void**)&c1p, g_c1);
  cudaGetSymbolAddress((void**)&h2p, g_h2);
  cudaGetSymbolAddress((void**)&c2p, g_c2);
  cudaGetSymbolAddress((void**)&yip, g_yi);

  gemm_np<4><<<dim3(1,8,48),256>>>(enc,256,NN*256,256, ih1W,0,
                                   nullptr,0,0,0, nullptr,0, ih1b,0, t1p,128,
                                   24, ih2W, ih2b, t2p);
  init_mix<<<B,128>>>(t1p,t2p,G,x,z);

  for(int t=0;t<T;t++){
    gemm_np<8><<<dim3(2,8,24),256>>>(xip,(long long)B*K0,K0,K0, Wx0,(long long)K0*G4,
                                     h1p,(long long)B*OUTF,OUTF,OUTF, Wh0,(long long)OUTF*G4,
                                     b0,G4, gp,G4, 24, nullptr,nullptr,nullptr);
    mix_lstm<<<B,256>>>(gp,G,h1p,c1p,nullptr);
    gemm_np<8><<<dim3(2,8,24),256>>>(h1p,(long long)B*OUTF,OUTF,OUTF, Wx1,(long long)OUTF*G4,
                                     h2p,(long long)B*OUTF,OUTF,OUTF, Wh1,(long long)OUTF*G4,
                                     b1,G4, gp,G4, 24, nullptr,nullptr,nullptr);
    mix_lstm<<<B,256>>>(gp,G,h2p,c2p,yip);
    gemm_np<4><<<dim3(1,8,48),256>>>(yip,(long long)B*OUTF,OUTF,OUTF, fcW,(long long)OUTF*OUTF,
                                     nullptr,0,0,0, nullptr,0, fcb,OUTF, t1p,OUTF,
                                     24, fc2W, fc2b, t2p);
    tail_step<<<B,256>>>(t,t1p,t2p,G,locW,locb,logzW,logzb,out);
  }
}

// round 9
// speedup vs baseline: 1.7044x; 1.0431x over previous
#include <cuda_runtime.h>
#include <math.h>

#define B 512
#define NN 24
#define T 25
#define OUTF 128
#define G4 512
#define K0 72

__device__ float g_xi[NN*B*K0];
__device__ float g_h1[NN*B*OUTF];
__device__ float g_c1[NN*B*OUTF];
__device__ float g_h2[NN*B*OUTF];
__device__ float g_c2[NN*B*OUTF];
__device__ float g_yi[NN*B*OUTF];
__device__ float g_gates[NN*B*G4];
__device__ float g_t1[NN*B*OUTF];
__device__ float g_t2[NN*B*OUTF];
__device__ float g_ls[NN*B*4];

typedef unsigned long long u64;
__device__ __forceinline__ u64 ffma2(u64 a,u64 b,u64 c){u64 d;asm("fma.rn.f32x2 %0,%1,%2,%3;":"=l"(d):"l"(a),"l"(b),"l"(c));return d;}
__device__ __forceinline__ u64 pk2(float x,float y){u64 r;asm("mov.b64 %0,{%1,%2};":"=l"(r):"f"(x),"f"(y));return r;}
__device__ __forceinline__ float2 upk2(u64 v){float2 r;asm("mov.b64 {%0,%1},%2;":"=f"(r.x),"=f"(r.y):"l"(v));return r;}

__device__ __forceinline__ float fex2(float x){float y;asm("ex2.approx.f32 %0,%1;":"=f"(y):"f"(x));return y;}
__device__ __forceinline__ float frcp(float x){float y;asm("rcp.approx.f32 %0,%1;":"=f"(y):"f"(x));return y;}
#define LOG2E 1.4426950408889634f
// tanh: saturates correctly for |x| large (ex2->inf => rcp->0 => 1; ex2->0 => -1)
__device__ __forceinline__ float ftanh(float x){ return 1.f - 2.f*frcp(fex2(2.f*LOG2E*x)+1.f); }
__device__ __forceinline__ float sigf (float x){ return frcp(1.f + fex2(-LOG2E*x)); }

// C[n][row][:NO] = bias[n] + A1[n,row,:K1]@W1[n] + A2[n,row,:K2]@W2[n]
// blockIdx.z >= nzA -> alternate (W1b, biasb, Cb) with same A1 (merged twin GEMMs).
template<int NPAIR>
__global__ __launch_bounds__(256,2) void gemm_np(
  const float* __restrict__ A1, long long sA1n, int sA1r, int K1,
  const float* __restrict__ W1, long long sW1n,
  const float* __restrict__ A2, long long sA2n, int sA2r, int K2,
  const float* __restrict__ W2, long long sW2n,
  const float* __restrict__ bias, int sbn,
  float* __restrict__ C, int NO, int nzA,
  const float* __restrict__ W1b, const float* __restrict__ biasb, float* __restrict__ Cb)
{
  constexpr int BN = 32*NPAIR;
  constexpr int WPT = BN/32;
  int n = blockIdx.z;
  if(n >= nzA){ n -= nzA; W1 = W1b; bias = biasb; C = Cb; }
  const int row0 = blockIdx.y*64, col0 = blockIdx.x*BN;
  const int tid = threadIdx.x;
  const int jj = tid&15, trow = (tid>>4)*4;
  const int la_r = tid>>2, la_k = (tid&3)*2;
  const int lw_k = tid>>5, lw_c = (tid&31)*WPT;

  __shared__ float As[2][8][64];
  __shared__ float Ws[2][8][BN];

  u64 acc[4][NPAIR];
  #pragma unroll
  for(int i=0;i<4;i++){
    #pragma unroll
    for(int t=0;t<NPAIR;t++) acc[i][t]=0ull;
  }

  const int n1 = K1>>3, n2 = K2>>3, nt = n1+n2;
  const float* pA1 = A1 + (long long)n*sA1n + (long long)(row0+la_r)*sA1r + la_k;
  const float* pW1 = W1 + (long long)n*sW1n + (long long)lw_k*NO + col0 + lw_c;
  const float* pA2 = (K2>0) ? A2 + (long long)n*sA2n + (long long)(row0+la_r)*sA2r + la_k : pA1;
  const float* pW2 = (K2>0) ? W2 + (long long)n*sW2n + (long long)lw_k*NO + col0 + lw_c : pW1;

  float2 aR;
  float4 wRa, wRb;
  auto loadit = [&](int it){
    const float* ap; const float* wp;
    if(it < n1){ ap = pA1 + it*8;      wp = pW1 + (long long)it*8*NO; }
    else       { ap = pA2 + (it-n1)*8; wp = pW2 + (long long)(it-n1)*8*NO; }
    aR = *(const float2*)ap;
    wRa = *(const float4*)wp;
    if(NPAIR==8) wRb = *(const float4*)(wp+4);
  };
  loadit(0);

  int cur = 0;
  for(int it=0; it<nt; ++it){
    As[cur][la_k  ][la_r] = aR.x;
    As[cur][la_k+1][la_r] = aR.y;
    *(float4*)&Ws[cur][lw_k][lw_c] = wRa;
    if(NPAIR==8) *(float4*)&Ws[cur][lw_k][lw_c+4] = wRb;
    __syncthreads();
    if(it+1 < nt) loadit(it+1);
    #pragma unroll
    for(int kk=0;kk<8;kk++){
      float4 av = *(const float4*)&As[cur][kk][trow];
      u64 ad0 = pk2(av.x,av.x), ad1 = pk2(av.y,av.y);
      u64 ad2 = pk2(av.z,av.z), ad3 = pk2(av.w,av.w);
      u64 wv[NPAIR];
      #pragma unroll
      for(int t=0;t<NPAIR;t++) wv[t] = *(const u64*)&Ws[cur][kk][2*jj+32*t];
      #pragma unroll
      for(int t=0;t<NPAIR;t++){
        acc[0][t] = ffma2(ad0, wv[t], acc[0][t]);
        acc[1][t] = ffma2(ad1, wv[t], acc[1][t]);
        acc[2][t] = ffma2(ad2, wv[t], acc[2][t]);
        acc[3][t] = ffma2(ad3, wv[t], acc[3][t]);
      }
    }
    cur ^= 1;
  }

  const float* bp = bias + (long long)n*sbn + col0;
  #pragma unroll
  for(int t=0;t<NPAIR;t++){
    float2 bv = *(const float2*)&bp[2*jj+32*t];
    #pragma unroll
    for(int i=0;i<4;i++){
      float2 p = upk2(acc[i][t]);
      *(float2*)&C[((long long)n*B+row0+trow+i)*NO + col0 + 2*jj + 32*t]
        = make_float2(p.x+bv.x, p.y+bv.y);
    }
  }
}

// G-mix of gates + LSTM pointwise. One CTA (256 threads) per batch element.
__global__ __launch_bounds__(256) void mix_lstm(
  const float* __restrict__ gates, const float* __restrict__ G,
  float* __restrict__ h, float* __restrict__ c, float* __restrict__ yi)
{
  const int b=blockIdx.x, tid=threadIdx.x;
  const int k = tid&127, half = tid>>7;
  __shared__ float Gs[NN*NN];
  __shared__ float stmp[NN][128];
  __shared__ float sf[NN][128];
  __shared__ float so[NN][128];
  for(int i=tid;i<NN*NN;i+=256) Gs[i]=G[i];
  __syncthreads();
  float a0[NN], a1[NN];
  #pragma unroll
  for(int m=0;m<NN;m++){a0[m]=0.f;a1[m]=0.f;}
  const float* gb0 = gates + (long long)b*G4 + k + (half?128:0);
  const float* gb1 = gates + (long long)b*G4 + k + (half?384:256);
  #pragma unroll 2
  for(int n=0;n<NN;n++){
    float ga = gb0[(long long)n*B*G4];
    float gg = gb1[(long long)n*B*G4];
    #pragma unroll
    for(int m=0;m<NN;m++){
      float gmn=Gs[m*NN+n];
      a0[m]+=gmn*ga; a1[m]+=gmn*gg;
    }
  }
  if(half==0){
    #pragma unroll
    for(int m=0;m<NN;m++) stmp[m][k]=sigf(a0[m])*ftanh(a1[m]);
  }else{
    #pragma unroll
    for(int m=0;m<NN;m++){ sf[m][k]=a0[m]; so[m][k]=a1[m]; }
  }
  __syncthreads();
  const int m0 = half*12;
  #pragma unroll
  for(int mm=0;mm<12;mm++){
    int m = m0+mm;
    long long idx=((long long)m*B+b)*OUTF+k;
    float cn=sigf(sf[m][k])*c[idx]+stmp[m][k];
    float hh=sigf(so[m][k])*ftanh(cn);
    c[idx]=cn; h[idx]=hh;
    if(yi) yi[idx]=ftanh(hh);
  }
}

// initial state: mix h0/c0 pre-activations, build xi0 and loc_start
__global__ __launch_bounds__(128) void init_mix(
  const float* __restrict__ t1, const float* __restrict__ t2,
  const float* __restrict__ G, const float* __restrict__ x, const float* __restrict__ z)
{
  const int b=blockIdx.x, k=threadIdx.x;
  __shared__ float Gs[NN*NN];
  __shared__ float s1[NN][OUTF], s2[NN][OUTF];
  for(int i=k;i<NN*NN;i+=128) Gs[i]=G[i];
  for(int tt=0;tt<6;tt++){
    int id=k+tt*128, n=id>>5, r=(id&31)*4;
    *(float4*)&s1[n][r]=*(const float4*)&t1[((long long)n*B+b)*OUTF+r];
    *(float4*)&s2[n][r]=*(const float4*)&t2[((long long)n*B+b)*OUTF+r];
  }
  __syncthreads();
  #pragma unroll 1
  for(int m=0;m<NN;m++){
    float hh=0.f, cc=0.f;
    for(int n=0;n<NN;n++){
      float gmn=Gs[m*NN+n];
      hh+=gmn*s1[n][k]; cc+=gmn*s2[n][k];
    }
    long long idx=((long long)m*B+b)*OUTF+k;
    g_h1[idx]=hh; g_h2[idx]=hh; g_c1[idx]=cc; g_c2[idx]=cc;
  }
  for(int id=k;id<NN*K0;id+=128){
    int n=id/K0, f=id%K0;
    float v=(f<64)? z[((long long)b*NN+n)*64+f] : x[((long long)b*NN+n)*8+(f-64)];
    g_xi[((long long)n*B+b)*K0+f]=v;
  }
  for(int id=k;id<NN*4;id+=128){
    int n=id>>2, j=id&3;
    g_ls[((long long)n*B+b)*4+j]=x[((long long)b*NN+n)*8+j];
  }
}

// per-step tail: mix+tanh of fc outputs (half-split, direct loads), warp-reduced
// loc/logz projections, second mix, quaternion chain, outputs, xi update.
__global__ __launch_bounds__(256) void tail_step(
  int t, const float* __restrict__ t1, const float* __restrict__ t2,
  const float* __restrict__ G,
  const float* __restrict__ locW, const float* __restrict__ locb,
  const float* __restrict__ logzW, const float* __restrict__ logzb,
  float* __restrict__ out)
{
  const int b=blockIdx.x, tid=threadIdx.x;
  const int k = tid&127, half = tid>>7;
  __shared__ float Gs[NN*NN];
  __shared__ float sy1[NN][128], sy2[NN][128];
  __shared__ float sw[7][128];
  __shared__ float q1[NN][4], q2[NN][4];
  for(int i=tid;i<NN*NN;i+=256) Gs[i]=G[i];
  for(int i=tid;i<7*128;i+=256){
    int j=i>>7, kk=i&127;
    sw[j][kk] = (j<3) ? locW[kk*3+j] : logzW[kk*4+(j-3)];
  }
  __syncthreads();
  {
    float a[NN];
    #pragma unroll
    for(int m=0;m<NN;m++) a[m]=0.f;
    const float* tp = (half? t2 : t1) + (long long)b*OUTF + k;
    #pragma unroll 2
    for(int n=0;n<NN;n++){
      float v = tp[(long long)n*B*OUTF];
      #pragma unroll
      for(int m=0;m<NN;m++) a[m]+=Gs[m*NN+n]*v;
    }
    if(half==0){
      #pragma unroll
      for(int m=0;m<NN;m++) sy1[m][k]=ftanh(a[m]);
    }else{
      #pragma unroll
      for(int m=0;m<NN;m++) sy2[m][k]=ftanh(a[m]);
    }
  }
  __syncthreads();
  // 168 projection tasks (24 m x 7 j), 8 warps x 21 tasks, warp-reduced
  {
    const int w = tid>>5, l = tid&31;
    #pragma unroll 1
    for(int i=0;i<21;i++){
      int tt = w*21+i;
      int m = tt/7, j = tt%7;
      const float* src = (j<3)? sy1[m] : sy2[m];
      float s0 = src[l]*sw[j][l] + src[l+64]*sw[j][l+64];
      float s1v= src[l+32]*sw[j][l+32] + src[l+96]*sw[j][l+96];
      float s = s0+s1v;
      #pragma unroll
      for(int o=16;o;o>>=1) s += __shfl_xor_sync(0xffffffffu,s,o);
      if(l==0){
        if(j<3) q1[m][j]=s+locb[j];
        else    q2[m][j-3]=s+logzb[j-3];
      }
    }
  }
  __syncthreads();
  if(tid<NN){
    int m=tid;
    float l0=0.f,l1=0.f,l2=0.f,z0=0.f,z1=0.f,z2=0.f,z3=0.f;
    for(int n=0;n<NN;n++){
      float gmn=Gs[m*NN+n];
      l0+=gmn*q1[n][0]; l1+=gmn*q1[n][1]; l2+=gmn*q1[n][2];
      z0+=gmn*q2[n][0]; z1+=gmn*q2[n][1]; z2+=gmn*q2[n][2]; z3+=gmn*q2[n][3];
    }
    float rn=rsqrtf(1.f+l0*l0+l1*l1+l2*l2);
    float dw=rn, dx=l0*rn, dy=l1*rn, dz=l2*rn;
    float4 ls=*(const float4*)&g_ls[((long long)m*B+b)*4];
    float qw=ls.x*dw - ls.y*dx - ls.z*dy - ls.w*dz;
    float qx=ls.x*dx + ls.y*dw + ls.z*dz - ls.w*dy;
    float qy=ls.x*dy - ls.y*dz + ls.z*dw + ls.w*dx;
    float qz=ls.x*dz + ls.y*dy - ls.z*dx + ls.w*dw;
    *(float4*)&g_ls[((long long)m*B+b)*4]=make_float4(qw,qx,qy,qz);
    long long ob=(((long long)b*T+t)*NN+m)*4;
    out[ob+0]=qw; out[ob+1]=qx; out[ob+2]=qy; out[ob+3]=qz;
    long long oz=(long long)B*T*NN*4+ob;
    out[oz+0]=z0; out[oz+1]=z1; out[oz+2]=z2; out[oz+3]=z3;
    float* xp=&g_xi[((long long)m*B+b)*K0+64];
    xp[0]=qw; xp[1]=qx; xp[2]=qy; xp[3]=qz;
    xp[4]=dw; xp[5]=dx; xp[6]=dy; xp[7]=dz;
  }
}

extern "C" void kernel_launch(void* const* d_in, const int* in_sizes, int n_in,
                              void* d_out, int out_size){
  const float* x    =(const float*)d_in[0];
  const float* enc  =(const float*)d_in[1];
  const float* z    =(const float*)d_in[2];
  const float* G    =(const float*)d_in[4];
  const float* Wx0  =(const float*)d_in[5];
  const float* Wh0  =(const float*)d_in[6];
  const float* b0   =(const float*)d_in[7];
  const float* Wx1  =(const float*)d_in[8];
  const float* Wh1  =(const float*)d_in[9];
  const float* b1   =(const float*)d_in[10];
  const float* fcW  =(const float*)d_in[11];
  const float* fcb  =(const float*)d_in[12];
  const float* fc2W =(const float*)d_in[13];
  const float* fc2b =(const float*)d_in[14];
  const float* ih1W =(const float*)d_in[15];
  const float* ih1b =(const float*)d_in[16];
  const float* ih2W =(const float*)d_in[17];
  const float* ih2b =(const float*)d_in[18];
  const float* locW =(const float*)d_in[19];
  const float* locb =(const float*)d_in[20];
  const float* logzW=(const float*)d_in[21];
  const float* logzb=(const float*)d_in[22];
  float* out=(float*)d_out;

  float *t1p,*t2p,*gp,*xip,*h1p,*c1p,*h2p,*c2p,*yip;
  cudaGetSymbolAddress((void**)&t1p, g_t1);
  cudaGetSymbolAddress((void**)&t2p, g_t2);
  cudaGetSymbolAddress((void**)&gp,  g_gates);
  cudaGetSymbolAddress((void**)&xip, g_xi);
  cudaGetSymbolAddress((void**)&h1p, g_h1);
  cudaGetSymbolAddress((void**)&c1p, g_c1);
  cudaGetSymbolAddress((void**)&h2p, g_h2);
  cudaGetSymbolAddress((void**)&c2p, g_c2);
  cudaGetSymbolAddress((void**)&yip, g_yi);

  gemm_np<4><<<dim3(1,8,48),256>>>(enc,256,NN*256,256, ih1W,0,
                                   nullptr,0,0,0, nullptr,0, ih1b,0, t1p,128,
                                   24, ih2W, ih2b, t2p);
  init_mix<<<B,128>>>(t1p,t2p,G,x,z);

  for(int t=0;t<T;t++){
    gemm_np<8><<<dim3(2,8,24),256>>>(xip,(long long)B*K0,K0,K0, Wx0,(long long)K0*G4,
                                     h1p,(long long)B*OUTF,OUTF,OUTF, Wh0,(long long)OUTF*G4,
                                     b0,G4, gp,G4, 24, nullptr,nullptr,nullptr);
    mix_lstm<<<B,256>>>(gp,G,h1p,c1p,nullptr);
    gemm_np<8><<<dim3(2,8,24),256>>>(h1p,(long long)B*OUTF,OUTF,OUTF, Wx1,(long long)OUTF*G4,
                                     h2p,(long long)B*OUTF,OUTF,OUTF, Wh1,(long long)OUTF*G4,
                                     b1,G4, gp,G4, 24, nullptr,nullptr,nullptr);
    mix_lstm<<<B,256>>>(gp,G,h2p,c2p,yip);
    gemm_np<4><<<dim3(1,8,48),256>>>(yip,(long long)B*OUTF,OUTF,OUTF, fcW,(long long)OUTF*OUTF,
                                     nullptr,0,0,0, nullptr,0, fcb,OUTF, t1p,OUTF,
                                     24, fc2W, fc2b, t2p);
    tail_step<<<B,256>>>(t,t1p,t2p,G,locW,locb,logzW,logzb,out);
  }
}